// round 14
// baseline (speedup 1.0000x reference)
#include <cuda_runtime.h>
#include <cuda_bf16.h>
#include <cuda_pipeline_primitives.h>
#include <mma.h>
#include <math.h>

using namespace nvcuda;

#define S_LEN 8192
#define HID   2048
#define HK    8
#define HV    16
#define DK    128
#define DV    128
#define CONVD 4096
#define CHUNK 64
#define NCHUNK 128
#define EPSF  1e-6f
#define QSCALE 0.08838834764831845f
#define TCK   2048
#define KC    32
#define NC    64

__device__ float g_mixed[S_LEN * CONVD];
__device__ float g_qn[S_LEN * HK * DK];
__device__ float g_kn[S_LEN * HK * DK];
__device__ float g_v [S_LEN * HV * DV];
__device__ float g_z [S_LEN * HV * DV];
__device__ float g_ba[S_LEN * 2 * HV];
__device__ float g_beta[S_LEN * HV];
__device__ float g_gc [S_LEN * HV];
__device__ float g_w  [S_LEN * HV * DV];
__device__ float g_u  [S_LEN * HV * DK];
__device__ float g_qg [S_LEN * HV * DK];
__device__ float g_kd [S_LEN * HV * DK];
__device__ float g_Aq [NCHUNK * HV * CHUNK * CHUNK];
__device__ float g_o  [S_LEN * HV * DV];

__device__ __nv_bfloat16 g_xhi[S_LEN * HID];
__device__ __nv_bfloat16 g_xlo[S_LEN * HID];
__device__ __nv_bfloat16 g_Bqh[CONVD * HID];
__device__ __nv_bfloat16 g_Bql[CONVD * HID];
__device__ __nv_bfloat16 g_Bzh[HID * HID];
__device__ __nv_bfloat16 g_Bzl[HID * HID];
__device__ __nv_bfloat16 g_Boh[HID * HID];
__device__ __nv_bfloat16 g_Bol[HID * HID];
__device__ __nv_bfloat16 g_ohi[S_LEN * HID];
__device__ __nv_bfloat16 g_olo[S_LEN * HID];

// stage one 128x32 bf16 tile (row stride 40 in smem) via cp.async, 16B per copy
__device__ __forceinline__ void stage_async(__nv_bfloat16* dst, const __nv_bfloat16* src,
                                            int kc, int t) {
    for (int e = t; e < 512; e += 256) {
        const int r = e >> 2;
        const int q = e & 3;
        __pipeline_memcpy_async(dst + r * 40 + q * 8, src + (size_t)r * TCK + kc + q * 8, 16);
    }
}

// ---- wmma GEMM: C[M,N] = (Ahi+Alo)[M,2048] @ (Bhi+Blo)[N,2048]^T, fp32 out ----
// block 256 thr = 8 warps (4x2), tile 128x128, warp tile 32x64, K chunk 32,
// cp.async double-buffered staging.
__global__ __launch_bounds__(256, 1)
void wmma_gemm(const __nv_bfloat16* __restrict__ Ahi, const __nv_bfloat16* __restrict__ Alo,
               const __nv_bfloat16* __restrict__ Bhi, const __nv_bfloat16* __restrict__ Blo,
               float* __restrict__ C, int N) {
    extern __shared__ __nv_bfloat16 smbf[];
    const int t = threadIdx.x;
    const int wid = t >> 5;
    const int wr = wid >> 1;
    const int wc = wid & 1;
    const int bM = blockIdx.y * 128;
    const int bN = blockIdx.x * 128;

    const __nv_bfloat16* Ah = Ahi + (size_t)bM * TCK;
    const __nv_bfloat16* Al = Alo + (size_t)bM * TCK;
    const __nv_bfloat16* Bh = Bhi + (size_t)bN * TCK;
    const __nv_bfloat16* Bl = Blo + (size_t)bN * TCK;

    wmma::fragment<wmma::accumulator, 16, 16, 16, float> acc[2][4];
    for (int i = 0; i < 2; i++) {
        for (int j = 0; j < 4; j++) {
            wmma::fill_fragment(acc[i][j], 0.0f);
        }
    }

    // buffer layout: buf*20480 + arr*5120 elements; arr order Ah, Al, Bh, Bl
    stage_async(smbf, Ah, 0, t);
    stage_async(smbf + 5120, Al, 0, t);
    stage_async(smbf + 10240, Bh, 0, t);
    stage_async(smbf + 15360, Bl, 0, t);
    __pipeline_commit();

    for (int c = 0; c < NC; c++) {
        if (c + 1 < NC) {
            __nv_bfloat16* nbuf = smbf + ((c + 1) & 1) * 20480;
            const int kc = (c + 1) * KC;
            stage_async(nbuf, Ah, kc, t);
            stage_async(nbuf + 5120, Al, kc, t);
            stage_async(nbuf + 10240, Bh, kc, t);
            stage_async(nbuf + 15360, Bl, kc, t);
            __pipeline_commit();
            __pipeline_wait_prior(1);
        } else {
            __pipeline_wait_prior(0);
        }
        __syncthreads();

        const __nv_bfloat16* sAh = smbf + (c & 1) * 20480;
        const __nv_bfloat16* sAl = sAh + 5120;
        const __nv_bfloat16* sBh = sAh + 10240;
        const __nv_bfloat16* sBl = sAh + 15360;

        for (int kk = 0; kk < KC; kk += 16) {
            wmma::fragment<wmma::matrix_a, 16, 16, 16, __nv_bfloat16, wmma::row_major> fah[2];
            wmma::fragment<wmma::matrix_a, 16, 16, 16, __nv_bfloat16, wmma::row_major> fal[2];
            for (int i = 0; i < 2; i++) {
                wmma::load_matrix_sync(fah[i], sAh + (wr * 32 + i * 16) * 40 + kk, 40);
                wmma::load_matrix_sync(fal[i], sAl + (wr * 32 + i * 16) * 40 + kk, 40);
            }
            for (int j = 0; j < 4; j++) {
                wmma::fragment<wmma::matrix_b, 16, 16, 16, __nv_bfloat16, wmma::col_major> fbh;
                wmma::fragment<wmma::matrix_b, 16, 16, 16, __nv_bfloat16, wmma::col_major> fbl;
                wmma::load_matrix_sync(fbh, sBh + (wc * 64 + j * 16) * 40 + kk, 40);
                wmma::load_matrix_sync(fbl, sBl + (wc * 64 + j * 16) * 40 + kk, 40);
                for (int i = 0; i < 2; i++) {
                    wmma::mma_sync(acc[i][j], fah[i], fbh, acc[i][j]);
                    wmma::mma_sync(acc[i][j], fah[i], fbl, acc[i][j]);
                    wmma::mma_sync(acc[i][j], fal[i], fbh, acc[i][j]);
                }
            }
        }
        __syncthreads();
    }

    for (int i = 0; i < 2; i++) {
        for (int j = 0; j < 4; j++) {
            float* cp = C + (size_t)(bM + wr * 32 + i * 16) * N + bN + wc * 64 + j * 16;
            wmma::store_matrix_sync(cp, acc[i][j], N, wmma::mem_row_major);
        }
    }
}

__global__ __launch_bounds__(256)
void split_kernel(const float* __restrict__ src, __nv_bfloat16* __restrict__ hi,
                  __nv_bfloat16* __restrict__ lo) {
    const int i = blockIdx.x * 256 + threadIdx.x;
    const float4 v = ((const float4*)src)[i];
    float a[4];
    a[0] = v.x; a[1] = v.y; a[2] = v.z; a[3] = v.w;
    for (int q = 0; q < 4; q++) {
        __nv_bfloat16 h = __float2bfloat16_rn(a[q]);
        hi[4 * i + q] = h;
        lo[4 * i + q] = __float2bfloat16_rn(a[q] - __bfloat162float(h));
    }
}

__global__ __launch_bounds__(256)
void tsplit_kernel(const float* __restrict__ src, __nv_bfloat16* __restrict__ hi,
                   __nv_bfloat16* __restrict__ lo, int R, int C) {
    __shared__ float tile[32][33];
    const int c0 = blockIdx.x * 32;
    const int r0 = blockIdx.y * 32;
    const int tx = threadIdx.x;
    const int ty = threadIdx.y;
    for (int j = 0; j < 32; j += 8) {
        tile[ty + j][tx] = src[(size_t)(r0 + ty + j) * C + c0 + tx];
    }
    __syncthreads();
    for (int j = 0; j < 32; j += 8) {
        float a = tile[tx][ty + j];
        __nv_bfloat16 h = __float2bfloat16_rn(a);
        size_t idx = (size_t)(c0 + ty + j) * R + r0 + tx;
        hi[idx] = h;
        lo[idx] = __float2bfloat16_rn(a - __bfloat162float(h));
    }
}

__global__ __launch_bounds__(256)
void ba_kernel(const float* __restrict__ x, const float* __restrict__ Wb,
               const float* __restrict__ Wa) {
    const int s = blockIdx.x;
    const int t = threadIdx.x;
    __shared__ float sx[HID];
    for (int e = t; e < HID; e += 256) sx[e] = x[(size_t)s * HID + e];
    __syncthreads();
    const int w = t >> 5;
    const int l = t & 31;
    for (int r = 0; r < 4; r++) {
        const int o = w * 4 + r;
        const float* Wp = (o < 16) ? Wb : Wa;
        const int hh = o & 15;
        float acc = 0.f;
        for (int kk = l; kk < HID; kk += 32) acc += sx[kk] * Wp[kk * 16 + hh];
        for (int sh = 16; sh; sh >>= 1) acc += __shfl_down_sync(0xffffffffu, acc, sh);
        if (l == 0) g_ba[s * 32 + o] = acc;
    }
}

__global__ __launch_bounds__(128)
void conv_kernel(const float* __restrict__ convw) {
    const int s = blockIdx.y;
    const int seg = blockIdx.x;
    const int d = threadIdx.x;
    const int col = seg * 128 + d;
    const float4 w4 = *(const float4*)&convw[col * 4];
    const size_t base = (size_t)s * CONVD + col;
    float m0 = (s >= 3) ? g_mixed[base - 3 * CONVD] : 0.f;
    float m1 = (s >= 2) ? g_mixed[base - 2 * CONVD] : 0.f;
    float m2 = (s >= 1) ? g_mixed[base - 1 * CONVD] : 0.f;
    float m3 = g_mixed[base];
    float acc = m0 * w4.x + m1 * w4.y + m2 * w4.z + m3 * w4.w;
    float val = acc / (1.f + __expf(-acc));
    if (seg < 16) {
        float ss = val * val;
        for (int o = 16; o; o >>= 1) ss += __shfl_down_sync(0xffffffffu, ss, o);
        __shared__ float wr[4];
        if ((d & 31) == 0) wr[d >> 5] = ss;
        __syncthreads();
        float rn = rsqrtf(wr[0] + wr[1] + wr[2] + wr[3] + EPSF);
        if (seg < 8) {
            g_qn[(size_t)s * (HK * DK) + seg * 128 + d] = val * rn * QSCALE;
        } else {
            g_kn[(size_t)s * (HK * DK) + (seg - 8) * 128 + d] = val * rn;
        }
    } else {
        g_v[(size_t)s * (HV * DV) + (seg - 16) * 128 + d] = val;
    }
}

__global__ __launch_bounds__(64)
void gate_kernel(const float* __restrict__ Alog, const float* __restrict__ dtb) {
    const int c = blockIdx.x >> 4;
    const int h = blockIdx.x & 15;
    const int t = threadIdx.x;
    const int s = c * CHUNK + t;
    const float bv = g_ba[s * 32 + h];
    const float av = g_ba[s * 32 + 16 + h];
    g_beta[s * HV + h] = 1.f / (1.f + __expf(-bv));
    const float xx = av + dtb[h];
    const float sp = fmaxf(xx, 0.f) + log1pf(__expf(-fabsf(xx)));
    float v = -__expf(Alog[h]) * sp;
    const int l = t & 31;
    const int w = t >> 5;
    for (int o = 1; o < 32; o <<= 1) {
        float n = __shfl_up_sync(0xffffffffu, v, o);
        if (l >= o) v += n;
    }
    __shared__ float ws;
    if (t == 31) ws = v;
    __syncthreads();
    if (w == 1) v += ws;
    g_gc[s * HV + h] = v;
}

__device__ __forceinline__ void tmul_out(const float* sT, const float* sX, float* dst, int t) {
    const int ty = t >> 4;
    const int tx = t & 15;
    float acc[4][8];
    for (int ii = 0; ii < 4; ii++) {
        for (int dd = 0; dd < 8; dd++) acc[ii][dd] = 0.f;
    }
    for (int j = 0; j < CHUNK; j++) {
        float tv[4];
        float vv[8];
        for (int ii = 0; ii < 4; ii++) tv[ii] = sT[(ty * 4 + ii) * 65 + j];
        for (int dd = 0; dd < 8; dd++) vv[dd] = sX[j * 129 + tx * 8 + dd];
        for (int ii = 0; ii < 4; ii++) {
            for (int dd = 0; dd < 8; dd++) acc[ii][dd] += tv[ii] * vv[dd];
        }
    }
    for (int ii = 0; ii < 4; ii++) {
        for (int dd = 0; dd < 8; dd++) {
            dst[(size_t)(ty * 4 + ii) * 2048 + tx * 8 + dd] = acc[ii][dd];
        }
    }
}

__global__ __launch_bounds__(256, 1)
void precompute_kernel() {
    const int blk = blockIdx.x;
    const int c = blk >> 4;
    const int h = blk & 15;
    const int kh = h >> 1;
    const int t = threadIdx.x;
    const int s0 = c * CHUNK;
    extern __shared__ float smf[];
    float* sQ = smf;
    float* sK = sQ + 64 * 129;
    float* sA = sK + 64 * 129;
    float* sT = sA + 64 * 65;
    float* sg = sT + 64 * 65;
    float* sb = sg + 64;

    if (t < 64) {
        sg[t] = g_gc[(s0 + t) * HV + h];
        sb[t] = g_beta[(s0 + t) * HV + h];
    }
    __syncthreads();
    const float glast = sg[63];

    for (int e = t; e < CHUNK * DK; e += 256) {
        const int i = e >> 7;
        const int d = e & 127;
        const float q = g_qn[(size_t)(s0 + i) * (HK * DK) + kh * DK + d];
        const float k = g_kn[(size_t)(s0 + i) * (HK * DK) + kh * DK + d];
        sQ[i * 129 + d] = q;
        sK[i * 129 + d] = k;
        const float gi = sg[i];
        g_qg[((size_t)(s0 + i) * HV + h) * DK + d] = q * __expf(gi);
        g_kd[((size_t)(s0 + i) * HV + h) * DK + d] = k * __expf(glast - gi);
    }
    __syncthreads();

    {
        const int ty = t >> 4;
        const int tx = t & 15;
        float akk[4][4];
        float aqk[4][4];
        for (int ii = 0; ii < 4; ii++) {
            for (int jj = 0; jj < 4; jj++) { akk[ii][jj] = 0.f; aqk[ii][jj] = 0.f; }
        }
        for (int d = 0; d < DK; d++) {
            float kj[4];
            float ki[4];
            float qi[4];
            for (int jj = 0; jj < 4; jj++) kj[jj] = sK[(tx + 16 * jj) * 129 + d];
            for (int ii = 0; ii < 4; ii++) {
                ki[ii] = sK[(ty + 16 * ii) * 129 + d];
                qi[ii] = sQ[(ty + 16 * ii) * 129 + d];
            }
            for (int ii = 0; ii < 4; ii++) {
                for (int jj = 0; jj < 4; jj++) {
                    akk[ii][jj] += ki[ii] * kj[jj];
                    aqk[ii][jj] += qi[ii] * kj[jj];
                }
            }
        }
        float* Aq = &g_Aq[(size_t)blk * CHUNK * CHUNK];
        for (int ii = 0; ii < 4; ii++) {
            const int i = ty + 16 * ii;
            for (int jj = 0; jj < 4; jj++) {
                const int j = tx + 16 * jj;
                const float ed = __expf(sg[i] - sg[j]);
                sA[i * 65 + j] = (j < i) ? (-sb[i] * akk[ii][jj] * ed) : 0.f;
                Aq[i * 64 + j] = (j <= i) ? (aqk[ii][jj] * ed) : 0.f;
            }
        }
    }
    __syncthreads();

    if (t < 64) {
        const int j = t;
        for (int i = 0; i < CHUNK; i++) {
            float acc = (i == j) ? 1.f : 0.f;
            for (int k = j; k < i; k++) acc += sA[i * 65 + k] * sT[k * 65 + j];
            sT[i * 65 + j] = acc;
        }
    }
    __syncthreads();

    for (int e = t; e < CHUNK * DV; e += 256) {
        const int i = e >> 7;
        const int d = e & 127;
        sQ[i * 129 + d] = g_v[(size_t)(s0 + i) * (HV * DV) + h * DV + d] * sb[i];
    }
    __syncthreads();
    tmul_out(sT, sQ, &g_w[((size_t)s0 * HV + h) * DV], t);
    __syncthreads();

    for (int e = t; e < CHUNK * DK; e += 256) {
        const int i = e >> 7;
        const int d = e & 127;
        sQ[i * 129 + d] = sK[i * 129 + d] * sb[i] * __expf(sg[i]);
    }
    __syncthreads();
    tmul_out(sT, sQ, &g_u[((size_t)s0 * HV + h) * DK], t);
}

__global__ __launch_bounds__(256, 1)
void scan_kernel() {
    const int h = blockIdx.y;
    const int dvoff = blockIdx.x * 16;
    const int t = threadIdx.x;
    __shared__ float sStage[64 * 129];
    __shared__ float sState[128 * 16];
    __shared__ float sVnew[64 * 16];

    for (int e = t; e < 128 * 16; e += 256) sState[e] = 0.f;
    __syncthreads();

    const int i4 = t >> 2;
    const int c4 = (t & 3) * 4;
    const int k2 = t >> 1;
    const int c8 = (t & 1) * 8;

    for (int c = 0; c < NCHUNK; c++) {
        const int s0 = c * CHUNK;
        const float eg = __expf(g_gc[(s0 + 63) * HV + h]);

        for (int e = t; e < CHUNK * DK; e += 256) {
            sStage[(e >> 7) * 129 + (e & 127)] = g_u[((size_t)(s0 + (e >> 7)) * HV + h) * DK + (e & 127)];
        }
        __syncthreads();

        float vn0, vn1, vn2, vn3;
        {
            float a0 = 0.f, a1 = 0.f, a2 = 0.f, a3 = 0.f;
            for (int k = 0; k < DK; k++) {
                const float uv = sStage[i4 * 129 + k];
                const float4 st = *(const float4*)&sState[k * 16 + c4];
                a0 += uv * st.x; a1 += uv * st.y; a2 += uv * st.z; a3 += uv * st.w;
            }
            const float4 wv = *(const float4*)&g_w[((size_t)(s0 + i4) * HV + h) * DV + dvoff + c4];
            vn0 = wv.x - a0; vn1 = wv.y - a1; vn2 = wv.z - a2; vn3 = wv.w - a3;
        }
        __syncthreads();
        *(float4*)&sVnew[i4 * 16 + c4] = make_float4(vn0, vn1, vn2, vn3);

        {
            const float* Aq = &g_Aq[((size_t)c * HV + h) * CHUNK * CHUNK];
            for (int e = t; e < CHUNK * CHUNK; e += 256) {
                sStage[(e >> 6) * 65 + (e & 63)] = Aq[e];
            }
        }
        __syncthreads();

        float o0 = 0.f, o1 = 0.f, o2 = 0.f, o3 = 0.f;
        for (int j = 0; j < CHUNK; j++) {
            const float aij = sStage[i4 * 65 + j];
            const float4 v = *(const float4*)&sVnew[j * 16 + c4];
            o0 += aij * v.x; o1 += aij * v.y; o2 += aij * v.z; o3 += aij * v.w;
        }
        __syncthreads();

        for (int e = t; e < CHUNK * DK; e += 256) {
            sStage[(e >> 7) * 129 + (e & 127)] = g_qg[((size_t)(s0 + (e >> 7)) * HV + h) * DK + (e & 127)];
        }
        __syncthreads();

        for (int k = 0; k < DK; k++) {
            const float qv = sStage[i4 * 129 + k];
            const float4 st = *(const float4*)&sState[k * 16 + c4];
            o0 += qv * st.x; o1 += qv * st.y; o2 += qv * st.z; o3 += qv * st.w;
        }
        *(float4*)&g_o[((size_t)(s0 + i4) * HV + h) * DV + dvoff + c4] = make_float4(o0, o1, o2, o3);
        __syncthreads();

        for (int e = t; e < CHUNK * DK; e += 256) {
            sStage[(e >> 7) * 129 + (e & 127)] = g_kd[((size_t)(s0 + (e >> 7)) * HV + h) * DK + (e & 127)];
        }
        __syncthreads();

        {
            float acc[8];
            for (int j = 0; j < 8; j++) acc[j] = 0.f;
            for (int i = 0; i < CHUNK; i++) {
                const float kv = sStage[i * 129 + k2];
                for (int j = 0; j < 8; j++) acc[j] += kv * sVnew[i * 16 + c8 + j];
            }
            for (int j = 0; j < 8; j++) {
                sState[k2 * 16 + c8 + j] = sState[k2 * 16 + c8 + j] * eg + acc[j];
            }
        }
        __syncthreads();
    }
}

__global__ __launch_bounds__(128)
void gating_kernel(const float* __restrict__ normw) {
    const int h = blockIdx.x;
    const int s = blockIdx.y;
    const int d = threadIdx.x;
    const size_t idx = ((size_t)s * HV + h) * DV + d;
    const float core = g_o[idx];
    float ss = core * core;
    for (int o = 16; o; o >>= 1) ss += __shfl_down_sync(0xffffffffu, ss, o);
    __shared__ float wr[4];
    if ((d & 31) == 0) wr[d >> 5] = ss;
    __syncthreads();
    const float mean = (wr[0] + wr[1] + wr[2] + wr[3]) * (1.f / DV);
    const float z = g_z[idx];
    const float val = core * rsqrtf(mean + EPSF) * normw[d] * (z / (1.f + __expf(-z)));
    const __nv_bfloat16 hi = __float2bfloat16_rn(val);
    g_ohi[idx] = hi;
    g_olo[idx] = __float2bfloat16_rn(val - __bfloat162float(hi));
}

extern "C" void kernel_launch(void* const* d_in, const int* in_sizes, int n_in,
                              void* d_out, int out_size) {
    const float* x      = (const float*)d_in[0];
    const float* W_qkv  = (const float*)d_in[1];
    const float* W_z    = (const float*)d_in[2];
    const float* W_b    = (const float*)d_in[3];
    const float* W_a    = (const float*)d_in[4];
    const float* conv_w = (const float*)d_in[5];
    const float* A_log  = (const float*)d_in[6];
    const float* dt_b   = (const float*)d_in[7];
    const float* norm_w = (const float*)d_in[8];
    const float* W_out  = (const float*)d_in[9];
    float* out = (float*)d_out;

    float* p_mixed;
    float* p_z;
    __nv_bfloat16* p_xhi;
    __nv_bfloat16* p_xlo;
    __nv_bfloat16* p_Bqh;
    __nv_bfloat16* p_Bql;
    __nv_bfloat16* p_Bzh;
    __nv_bfloat16* p_Bzl;
    __nv_bfloat16* p_Boh;
    __nv_bfloat16* p_Bol;
    __nv_bfloat16* p_ohi;
    __nv_bfloat16* p_olo;
    cudaGetSymbolAddress((void**)&p_mixed, g_mixed);
    cudaGetSymbolAddress((void**)&p_z, g_z);
    cudaGetSymbolAddress((void**)&p_xhi, g_xhi);
    cudaGetSymbolAddress((void**)&p_xlo, g_xlo);
    cudaGetSymbolAddress((void**)&p_Bqh, g_Bqh);
    cudaGetSymbolAddress((void**)&p_Bql, g_Bql);
    cudaGetSymbolAddress((void**)&p_Bzh, g_Bzh);
    cudaGetSymbolAddress((void**)&p_Bzl, g_Bzl);
    cudaGetSymbolAddress((void**)&p_Boh, g_Boh);
    cudaGetSymbolAddress((void**)&p_Bol, g_Bol);
    cudaGetSymbolAddress((void**)&p_ohi, g_ohi);
    cudaGetSymbolAddress((void**)&p_olo, g_olo);

    const int gemm_smem = 2 * 4 * 128 * 40 * 2;
    cudaFuncSetAttribute(wmma_gemm, cudaFuncAttributeMaxDynamicSharedMemorySize, gemm_smem);
    const int pre_smem = (64 * 129 * 2 + 64 * 65 * 2 + 128) * 4;
    cudaFuncSetAttribute(precompute_kernel, cudaFuncAttributeMaxDynamicSharedMemorySize, pre_smem);

    split_kernel<<<S_LEN * HID / 1024, 256>>>(x, p_xhi, p_xlo);
    tsplit_kernel<<<dim3(CONVD / 32, HID / 32), dim3(32, 8)>>>(W_qkv, p_Bqh, p_Bql, HID, CONVD);
    tsplit_kernel<<<dim3(HID / 32, HID / 32), dim3(32, 8)>>>(W_z, p_Bzh, p_Bzl, HID, HID);
    tsplit_kernel<<<dim3(HID / 32, HID / 32), dim3(32, 8)>>>(W_out, p_Boh, p_Bol, HID, HID);

    wmma_gemm<<<dim3(CONVD / 128, S_LEN / 128), 256, gemm_smem>>>(p_xhi, p_xlo, p_Bqh, p_Bql, p_mixed, CONVD);
    wmma_gemm<<<dim3(HID / 128, S_LEN / 128), 256, gemm_smem>>>(p_xhi, p_xlo, p_Bzh, p_Bzl, p_z, HID);

    ba_kernel<<<S_LEN, 256>>>(x, W_b, W_a);
    conv_kernel<<<dim3(32, S_LEN), 128>>>(conv_w);
    gate_kernel<<<NCHUNK * HV, 64>>>(A_log, dt_b);
    precompute_kernel<<<NCHUNK * HV, 256, pre_smem>>>();
    scan_kernel<<<dim3(8, HV), 256>>>();
    gating_kernel<<<dim3(HV, S_LEN), 128>>>(norm_w);

    wmma_gemm<<<dim3(HID / 128, S_LEN / 128), 256, gemm_smem>>>(p_ohi, p_olo, p_Boh, p_Bol, out, HID);
}

// round 15
// speedup vs baseline: 1.8259x; 1.8259x over previous
#include <cuda_runtime.h>
#include <cuda_bf16.h>
#include <cuda_fp16.h>
#include <mma.h>
#include <math.h>

using namespace nvcuda;

#define S_LEN 8192
#define HID   2048
#define HK    8
#define HV    16
#define DK    128
#define DV    128
#define CONVD 4096
#define CHUNK 64
#define NCHUNK 128
#define EPSF  1e-6f
#define QSCALE 0.08838834764831845f
#define TCK   2048
#define KC    32
#define NC    64

__device__ float g_mixed[S_LEN * CONVD];
__device__ float g_qn[S_LEN * HK * DK];
__device__ float g_kn[S_LEN * HK * DK];
__device__ float g_v [S_LEN * HV * DV];
__device__ float g_z [S_LEN * HV * DV];
__device__ float g_ba[S_LEN * 2 * HV];
__device__ float g_beta[S_LEN * HV];
__device__ float g_gc [S_LEN * HV];
__device__ float g_w  [S_LEN * HV * DV];
__device__ float g_u  [S_LEN * HV * DK];
__device__ float g_qg [S_LEN * HV * DK];
__device__ float g_kd [S_LEN * HV * DK];
__device__ float g_Aq [NCHUNK * HV * CHUNK * CHUNK];
__device__ float g_o  [S_LEN * HV * DV];

__device__ __half g_xh [S_LEN * HID];
__device__ __half g_Bq [CONVD * HID];
__device__ __half g_Bz [HID * HID];
__device__ __half g_Bo [HID * HID];
__device__ __half g_oh [S_LEN * HID];

// ---- wmma GEMM: C[M,N] = A[M,2048]fp16 @ B[N,2048]fp16^T, fp32 out ----
// block 256 thr = 8 warps (4x2), tile 128x128, warp tile 32x64, K chunk 32
__global__ __launch_bounds__(256)
void wmma_gemm(const __half* __restrict__ A, const __half* __restrict__ B,
               float* __restrict__ C, int N) {
    __shared__ __half sA[128][40];
    __shared__ __half sB[128][40];
    const int t = threadIdx.x;
    const int wid = t >> 5;
    const int wr = wid >> 1;
    const int wc = wid & 1;
    const int bM = blockIdx.y * 128;
    const int bN = blockIdx.x * 128;

    const __half* Ap = A + (size_t)bM * TCK;
    const __half* Bp = B + (size_t)bN * TCK;

    wmma::fragment<wmma::accumulator, 16, 16, 16, float> acc[2][4];
    for (int i = 0; i < 2; i++) {
        for (int j = 0; j < 4; j++) {
            wmma::fill_fragment(acc[i][j], 0.0f);
        }
    }

    for (int kc = 0; kc < TCK; kc += KC) {
        for (int e = t; e < 512; e += 256) {
            const int r = e >> 2;
            const int q = (e & 3) * 8;
            *(uint4*)&sA[r][q] = *(const uint4*)(Ap + (size_t)r * TCK + kc + q);
            *(uint4*)&sB[r][q] = *(const uint4*)(Bp + (size_t)r * TCK + kc + q);
        }
        __syncthreads();
        for (int kk = 0; kk < KC; kk += 16) {
            wmma::fragment<wmma::matrix_a, 16, 16, 16, __half, wmma::row_major> fa[2];
            for (int i = 0; i < 2; i++) {
                wmma::load_matrix_sync(fa[i], &sA[wr * 32 + i * 16][kk], 40);
            }
            for (int j = 0; j < 4; j++) {
                wmma::fragment<wmma::matrix_b, 16, 16, 16, __half, wmma::col_major> fb;
                wmma::load_matrix_sync(fb, &sB[wc * 64 + j * 16][kk], 40);
                for (int i = 0; i < 2; i++) {
                    wmma::mma_sync(acc[i][j], fa[i], fb, acc[i][j]);
                }
            }
        }
        __syncthreads();
    }
    for (int i = 0; i < 2; i++) {
        for (int j = 0; j < 4; j++) {
            float* cp = C + (size_t)(bM + wr * 32 + i * 16) * N + bN + wc * 64 + j * 16;
            wmma::store_matrix_sync(cp, acc[i][j], N, wmma::mem_row_major);
        }
    }
}

__global__ __launch_bounds__(256)
void tohalf_kernel(const float* __restrict__ src, __half* __restrict__ dst) {
    const int i = blockIdx.x * 256 + threadIdx.x;
    const float4 v = ((const float4*)src)[i];
    __half2 h0;
    __half2 h1;
    h0 = __floats2half2_rn(v.x, v.y);
    h1 = __floats2half2_rn(v.z, v.w);
    ((__half2*)dst)[2 * i] = h0;
    ((__half2*)dst)[2 * i + 1] = h1;
}

__global__ __launch_bounds__(256)
void ttrans_kernel(const float* __restrict__ src, __half* __restrict__ dst, int R, int C) {
    __shared__ float tile[32][33];
    const int c0 = blockIdx.x * 32;
    const int r0 = blockIdx.y * 32;
    const int tx = threadIdx.x;
    const int ty = threadIdx.y;
    for (int j = 0; j < 32; j += 8) {
        tile[ty + j][tx] = src[(size_t)(r0 + ty + j) * C + c0 + tx];
    }
    __syncthreads();
    for (int j = 0; j < 32; j += 8) {
        dst[(size_t)(c0 + ty + j) * R + r0 + tx] = __float2half_rn(tile[tx][ty + j]);
    }
}

__global__ __launch_bounds__(256)
void ba_kernel(const float* __restrict__ x, const float* __restrict__ Wb,
               const float* __restrict__ Wa) {
    const int s = blockIdx.x;
    const int t = threadIdx.x;
    __shared__ float sx[HID];
    for (int e = t; e < HID; e += 256) sx[e] = x[(size_t)s * HID + e];
    __syncthreads();
    const int w = t >> 5;
    const int l = t & 31;
    for (int r = 0; r < 4; r++) {
        const int o = w * 4 + r;
        const float* Wp = (o < 16) ? Wb : Wa;
        const int hh = o & 15;
        float acc = 0.f;
        for (int kk = l; kk < HID; kk += 32) acc += sx[kk] * Wp[kk * 16 + hh];
        for (int sh = 16; sh; sh >>= 1) acc += __shfl_down_sync(0xffffffffu, acc, sh);
        if (l == 0) g_ba[s * 32 + o] = acc;
    }
}

__global__ __launch_bounds__(128)
void conv_kernel(const float* __restrict__ convw) {
    const int s = blockIdx.y;
    const int seg = blockIdx.x;
    const int d = threadIdx.x;
    const int col = seg * 128 + d;
    const float4 w4 = *(const float4*)&convw[col * 4];
    const size_t base = (size_t)s * CONVD + col;
    float m0 = (s >= 3) ? g_mixed[base - 3 * CONVD] : 0.f;
    float m1 = (s >= 2) ? g_mixed[base - 2 * CONVD] : 0.f;
    float m2 = (s >= 1) ? g_mixed[base - 1 * CONVD] : 0.f;
    float m3 = g_mixed[base];
    float acc = m0 * w4.x + m1 * w4.y + m2 * w4.z + m3 * w4.w;
    float val = acc / (1.f + __expf(-acc));
    if (seg < 16) {
        float ss = val * val;
        for (int o = 16; o; o >>= 1) ss += __shfl_down_sync(0xffffffffu, ss, o);
        __shared__ float wr[4];
        if ((d & 31) == 0) wr[d >> 5] = ss;
        __syncthreads();
        float rn = rsqrtf(wr[0] + wr[1] + wr[2] + wr[3] + EPSF);
        if (seg < 8) {
            g_qn[(size_t)s * (HK * DK) + seg * 128 + d] = val * rn * QSCALE;
        } else {
            g_kn[(size_t)s * (HK * DK) + (seg - 8) * 128 + d] = val * rn;
        }
    } else {
        g_v[(size_t)s * (HV * DV) + (seg - 16) * 128 + d] = val;
    }
}

__global__ __launch_bounds__(64)
void gate_kernel(const float* __restrict__ Alog, const float* __restrict__ dtb) {
    const int c = blockIdx.x >> 4;
    const int h = blockIdx.x & 15;
    const int t = threadIdx.x;
    const int s = c * CHUNK + t;
    const float bv = g_ba[s * 32 + h];
    const float av = g_ba[s * 32 + 16 + h];
    g_beta[s * HV + h] = 1.f / (1.f + __expf(-bv));
    const float xx = av + dtb[h];
    const float sp = fmaxf(xx, 0.f) + log1pf(__expf(-fabsf(xx)));
    float v = -__expf(Alog[h]) * sp;
    const int l = t & 31;
    const int w = t >> 5;
    for (int o = 1; o < 32; o <<= 1) {
        float n = __shfl_up_sync(0xffffffffu, v, o);
        if (l >= o) v += n;
    }
    __shared__ float ws;
    if (t == 31) ws = v;
    __syncthreads();
    if (w == 1) v += ws;
    g_gc[s * HV + h] = v;
}

__device__ __forceinline__ void tmul_out(const float* sT, const float* sX, float* dst, int t) {
    const int ty = t >> 4;
    const int tx = t & 15;
    float acc[4][8];
    for (int ii = 0; ii < 4; ii++) {
        for (int dd = 0; dd < 8; dd++) acc[ii][dd] = 0.f;
    }
    for (int j = 0; j < CHUNK; j++) {
        float tv[4];
        float vv[8];
        for (int ii = 0; ii < 4; ii++) tv[ii] = sT[(ty * 4 + ii) * 65 + j];
        for (int dd = 0; dd < 8; dd++) vv[dd] = sX[j * 129 + tx * 8 + dd];
        for (int ii = 0; ii < 4; ii++) {
            for (int dd = 0; dd < 8; dd++) acc[ii][dd] += tv[ii] * vv[dd];
        }
    }
    for (int ii = 0; ii < 4; ii++) {
        for (int dd = 0; dd < 8; dd++) {
            dst[(size_t)(ty * 4 + ii) * 2048 + tx * 8 + dd] = acc[ii][dd];
        }
    }
}

__global__ __launch_bounds__(256, 1)
void precompute_kernel() {
    const int blk = blockIdx.x;
    const int c = blk >> 4;
    const int h = blk & 15;
    const int kh = h >> 1;
    const int t = threadIdx.x;
    const int s0 = c * CHUNK;
    extern __shared__ float smf[];
    float* sQ = smf;
    float* sK = sQ + 64 * 129;
    float* sA = sK + 64 * 129;
    float* sT = sA + 64 * 65;
    float* sg = sT + 64 * 65;
    float* sb = sg + 64;

    if (t < 64) {
        sg[t] = g_gc[(s0 + t) * HV + h];
        sb[t] = g_beta[(s0 + t) * HV + h];
    }
    __syncthreads();
    const float glast = sg[63];

    for (int e = t; e < CHUNK * DK; e += 256) {
        const int i = e >> 7;
        const int d = e & 127;
        const float q = g_qn[(size_t)(s0 + i) * (HK * DK) + kh * DK + d];
        const float k = g_kn[(size_t)(s0 + i) * (HK * DK) + kh * DK + d];
        sQ[i * 129 + d] = q;
        sK[i * 129 + d] = k;
        const float gi = sg[i];
        g_qg[((size_t)(s0 + i) * HV + h) * DK + d] = q * __expf(gi);
        g_kd[((size_t)(s0 + i) * HV + h) * DK + d] = k * __expf(glast - gi);
    }
    __syncthreads();

    {
        const int ty = t >> 4;
        const int tx = t & 15;
        float akk[4][4];
        float aqk[4][4];
        for (int ii = 0; ii < 4; ii++) {
            for (int jj = 0; jj < 4; jj++) { akk[ii][jj] = 0.f; aqk[ii][jj] = 0.f; }
        }
        for (int d = 0; d < DK; d++) {
            float kj[4];
            float ki[4];
            float qi[4];
            for (int jj = 0; jj < 4; jj++) kj[jj] = sK[(tx + 16 * jj) * 129 + d];
            for (int ii = 0; ii < 4; ii++) {
                ki[ii] = sK[(ty + 16 * ii) * 129 + d];
                qi[ii] = sQ[(ty + 16 * ii) * 129 + d];
            }
            for (int ii = 0; ii < 4; ii++) {
                for (int jj = 0; jj < 4; jj++) {
                    akk[ii][jj] += ki[ii] * kj[jj];
                    aqk[ii][jj] += qi[ii] * kj[jj];
                }
            }
        }
        float* Aq = &g_Aq[(size_t)blk * CHUNK * CHUNK];
        for (int ii = 0; ii < 4; ii++) {
            const int i = ty + 16 * ii;
            for (int jj = 0; jj < 4; jj++) {
                const int j = tx + 16 * jj;
                const float ed = __expf(sg[i] - sg[j]);
                sA[i * 65 + j] = (j < i) ? (-sb[i] * akk[ii][jj] * ed) : 0.f;
                Aq[i * 64 + j] = (j <= i) ? (aqk[ii][jj] * ed) : 0.f;
            }
        }
    }
    __syncthreads();

    if (t < 64) {
        const int j = t;
        for (int i = 0; i < CHUNK; i++) {
            float acc = (i == j) ? 1.f : 0.f;
            for (int k = j; k < i; k++) acc += sA[i * 65 + k] * sT[k * 65 + j];
            sT[i * 65 + j] = acc;
        }
    }
    __syncthreads();

    for (int e = t; e < CHUNK * DV; e += 256) {
        const int i = e >> 7;
        const int d = e & 127;
        sQ[i * 129 + d] = g_v[(size_t)(s0 + i) * (HV * DV) + h * DV + d] * sb[i];
    }
    __syncthreads();
    tmul_out(sT, sQ, &g_w[((size_t)s0 * HV + h) * DV], t);
    __syncthreads();

    for (int e = t; e < CHUNK * DK; e += 256) {
        const int i = e >> 7;
        const int d = e & 127;
        sQ[i * 129 + d] = sK[i * 129 + d] * sb[i] * __expf(sg[i]);
    }
    __syncthreads();
    tmul_out(sT, sQ, &g_u[((size_t)s0 * HV + h) * DK], t);
}

__global__ __launch_bounds__(256, 1)
void scan_kernel() {
    const int h = blockIdx.y;
    const int dvoff = blockIdx.x * 16;
    const int t = threadIdx.x;
    __shared__ float sStage[64 * 129];
    __shared__ float sState[128 * 16];
    __shared__ float sVnew[64 * 16];

    for (int e = t; e < 128 * 16; e += 256) sState[e] = 0.f;
    __syncthreads();

    const int i4 = t >> 2;
    const int c4 = (t & 3) * 4;
    const int k2 = t >> 1;
    const int c8 = (t & 1) * 8;

    for (int c = 0; c < NCHUNK; c++) {
        const int s0 = c * CHUNK;
        const float eg = __expf(g_gc[(s0 + 63) * HV + h]);

        for (int e = t; e < CHUNK * DK; e += 256) {
            sStage[(e >> 7) * 129 + (e & 127)] = g_u[((size_t)(s0 + (e >> 7)) * HV + h) * DK + (e & 127)];
        }
        __syncthreads();

        float vn0, vn1, vn2, vn3;
        {
            float a0 = 0.f, a1 = 0.f, a2 = 0.f, a3 = 0.f;
            for (int k = 0; k < DK; k++) {
                const float uv = sStage[i4 * 129 + k];
                const float4 st = *(const float4*)&sState[k * 16 + c4];
                a0 += uv * st.x; a1 += uv * st.y; a2 += uv * st.z; a3 += uv * st.w;
            }
            const float4 wv = *(const float4*)&g_w[((size_t)(s0 + i4) * HV + h) * DV + dvoff + c4];
            vn0 = wv.x - a0; vn1 = wv.y - a1; vn2 = wv.z - a2; vn3 = wv.w - a3;
        }
        __syncthreads();
        *(float4*)&sVnew[i4 * 16 + c4] = make_float4(vn0, vn1, vn2, vn3);

        {
            const float* Aq = &g_Aq[((size_t)c * HV + h) * CHUNK * CHUNK];
            for (int e = t; e < CHUNK * CHUNK; e += 256) {
                sStage[(e >> 6) * 65 + (e & 63)] = Aq[e];
            }
        }
        __syncthreads();

        float o0 = 0.f, o1 = 0.f, o2 = 0.f, o3 = 0.f;
        for (int j = 0; j < CHUNK; j++) {
            const float aij = sStage[i4 * 65 + j];
            const float4 v = *(const float4*)&sVnew[j * 16 + c4];
            o0 += aij * v.x; o1 += aij * v.y; o2 += aij * v.z; o3 += aij * v.w;
        }
        __syncthreads();

        for (int e = t; e < CHUNK * DK; e += 256) {
            sStage[(e >> 7) * 129 + (e & 127)] = g_qg[((size_t)(s0 + (e >> 7)) * HV + h) * DK + (e & 127)];
        }
        __syncthreads();

        for (int k = 0; k < DK; k++) {
            const float qv = sStage[i4 * 129 + k];
            const float4 st = *(const float4*)&sState[k * 16 + c4];
            o0 += qv * st.x; o1 += qv * st.y; o2 += qv * st.z; o3 += qv * st.w;
        }
        *(float4*)&g_o[((size_t)(s0 + i4) * HV + h) * DV + dvoff + c4] = make_float4(o0, o1, o2, o3);
        __syncthreads();

        for (int e = t; e < CHUNK * DK; e += 256) {
            sStage[(e >> 7) * 129 + (e & 127)] = g_kd[((size_t)(s0 + (e >> 7)) * HV + h) * DK + (e & 127)];
        }
        __syncthreads();

        {
            float acc[8];
            for (int j = 0; j < 8; j++) acc[j] = 0.f;
            for (int i = 0; i < CHUNK; i++) {
                const float kv = sStage[i * 129 + k2];
                for (int j = 0; j < 8; j++) acc[j] += kv * sVnew[i * 16 + c8 + j];
            }
            for (int j = 0; j < 8; j++) {
                sState[k2 * 16 + c8 + j] = sState[k2 * 16 + c8 + j] * eg + acc[j];
            }
        }
        __syncthreads();
    }
}

__global__ __launch_bounds__(128)
void gating_kernel(const float* __restrict__ normw) {
    const int h = blockIdx.x;
    const int s = blockIdx.y;
    const int d = threadIdx.x;
    const size_t idx = ((size_t)s * HV + h) * DV + d;
    const float core = g_o[idx];
    float ss = core * core;
    for (int o = 16; o; o >>= 1) ss += __shfl_down_sync(0xffffffffu, ss, o);
    __shared__ float wr[4];
    if ((d & 31) == 0) wr[d >> 5] = ss;
    __syncthreads();
    const float mean = (wr[0] + wr[1] + wr[2] + wr[3]) * (1.f / DV);
    const float z = g_z[idx];
    const float val = core * rsqrtf(mean + EPSF) * normw[d] * (z / (1.f + __expf(-z)));
    g_oh[idx] = __float2half_rn(val);
}

extern "C" void kernel_launch(void* const* d_in, const int* in_sizes, int n_in,
                              void* d_out, int out_size) {
    const float* x      = (const float*)d_in[0];
    const float* W_qkv  = (const float*)d_in[1];
    const float* W_z    = (const float*)d_in[2];
    const float* W_b    = (const float*)d_in[3];
    const float* W_a    = (const float*)d_in[4];
    const float* conv_w = (const float*)d_in[5];
    const float* A_log  = (const float*)d_in[6];
    const float* dt_b   = (const float*)d_in[7];
    const float* norm_w = (const float*)d_in[8];
    const float* W_out  = (const float*)d_in[9];
    float* out = (float*)d_out;

    float* p_mixed;
    float* p_z;
    __half* p_xh;
    __half* p_Bq;
    __half* p_Bz;
    __half* p_Bo;
    __half* p_oh;
    cudaGetSymbolAddress((void**)&p_mixed, g_mixed);
    cudaGetSymbolAddress((void**)&p_z, g_z);
    cudaGetSymbolAddress((void**)&p_xh, g_xh);
    cudaGetSymbolAddress((void**)&p_Bq, g_Bq);
    cudaGetSymbolAddress((void**)&p_Bz, g_Bz);
    cudaGetSymbolAddress((void**)&p_Bo, g_Bo);
    cudaGetSymbolAddress((void**)&p_oh, g_oh);

    const int pre_smem = (64 * 129 * 2 + 64 * 65 * 2 + 128) * 4;
    cudaFuncSetAttribute(precompute_kernel, cudaFuncAttributeMaxDynamicSharedMemorySize, pre_smem);

    tohalf_kernel<<<S_LEN * HID / 1024, 256>>>(x, p_xh);
    ttrans_kernel<<<dim3(CONVD / 32, HID / 32), dim3(32, 8)>>>(W_qkv, p_Bq, HID, CONVD);
    ttrans_kernel<<<dim3(HID / 32, HID / 32), dim3(32, 8)>>>(W_z, p_Bz, HID, HID);
    ttrans_kernel<<<dim3(HID / 32, HID / 32), dim3(32, 8)>>>(W_out, p_Bo, HID, HID);

    wmma_gemm<<<dim3(CONVD / 128, S_LEN / 128), 256>>>(p_xh, p_Bq, p_mixed, CONVD);
    wmma_gemm<<<dim3(HID / 128, S_LEN / 128), 256>>>(p_xh, p_Bz, p_z, HID);

    ba_kernel<<<S_LEN, 256>>>(x, W_b, W_a);
    conv_kernel<<<dim3(32, S_LEN), 128>>>(conv_w);
    gate_kernel<<<NCHUNK * HV, 64>>>(A_log, dt_b);
    precompute_kernel<<<NCHUNK * HV, 256, pre_smem>>>();
    scan_kernel<<<dim3(8, HV), 256>>>();
    gating_kernel<<<dim3(HV, S_LEN), 128>>>(norm_w);

    wmma_gemm<<<dim3(HID / 128, S_LEN / 128), 256>>>(p_oh, p_Bo, out, HID);
}